// round 13
// baseline (speedup 1.0000x reference)
#include <cuda_runtime.h>
#include <math_constants.h>

// ---- problem constants ----
#define BG     4        // graphs
#define NN     16384    // nodes per graph
#define KK     8192     // kept per graph
#define KNN    6
#define DD     128
#define TOTK   32768    // BG*KK
#define EE     196608   // TOTK*KNN (one direction)

// output section offsets (float32 elements), tuple order flattened+concat
#define OFF_XC    0
#define OFF_POSC  4194304
#define OFF_EA    4292608
#define OFF_EI    5865472
#define OFF_PERM  6651904
#define OFF_NT    6684672
#define OFF_BATCH 6717440

// scratch (no allocations allowed)
__device__ int    g_perm[TOTK];
__device__ float4 g_posc[TOTK];   // x,y,z, sq

// Reference d2 rounding:
//   sq  = fma(z,z, fma(x,x, fl(y*y)))   [XLA unrolled reduce (x^2+y^2)+z^2,
//                                        LLVM left-assoc fadd->fma contraction]
//   dot = fma(z,cz, fma(y,cy, fl(x*cx)))  [cublas K=3: ascending single-acc]
//   d2  = fl( fl(sq_i + sq_j) - fl(2*dot) )
__device__ __forceinline__ float d2_ref(float4 a, float4 b) {
    float t = __fmul_rn(a.x, b.x);
    t = __fmaf_rn(a.y, b.y, t);
    t = __fmaf_rn(a.z, b.z, t);
    return __fsub_rn(__fadd_rn(a.w, b.w), __fadd_rn(t, t));
}

__device__ __forceinline__ float sq_ref(float px, float py, float pz) {
    // (x^2 + y^2) + z^2 contracted left-assoc: fma(z,z, fma(x,x, fl(y*y)))
    return __fmaf_rn(pz, pz, __fmaf_rn(px, px, __fmul_rn(py, py)));
}

// ---------------------------------------------------------------------------
// Kernel 1: per-graph descending sort of scores (bitonic, 16384 u64 keys in
// 128KB dynamic smem) -> perm, pos_c, node_type_c, batch_c. (bit-exact ✓)
// ---------------------------------------------------------------------------
extern __shared__ unsigned long long s_keys[];

__global__ void topk_kernel(const float* __restrict__ attn,
                            const float* __restrict__ pos,
                            const int*   __restrict__ node_type,
                            float* __restrict__ out) {
    const int g   = blockIdx.x;
    const int tid = threadIdx.x;
    const int NT  = blockDim.x;

    for (int i = tid; i < NN; i += NT) {
        unsigned u = __float_as_uint(attn[g * NN + i]);
        u = (u & 0x80000000u) ? ~u : (u | 0x80000000u);
        s_keys[i] = ((unsigned long long)(~u) << 32) | (unsigned)i;
    }
    __syncthreads();

    for (int k = 2; k <= NN; k <<= 1) {
        for (int j = k >> 1; j > 0; j >>= 1) {
            for (int i = tid; i < NN; i += NT) {
                int ixj = i ^ j;
                if (ixj > i) {
                    unsigned long long a = s_keys[i];
                    unsigned long long b = s_keys[ixj];
                    bool up = ((i & k) == 0);
                    if ((a > b) == up) { s_keys[i] = b; s_keys[ixj] = a; }
                }
            }
            __syncthreads();
        }
    }

    for (int r = tid; r < KK; r += NT) {
        int il  = (int)(s_keys[r] & 0xFFFFFFFFull);
        int pv  = g * NN + il;
        int row = g * KK + r;
        g_perm[row] = pv;
        out[OFF_PERM + row] = (float)pv;

        float px = pos[pv * 3 + 0];
        float py = pos[pv * 3 + 1];
        float pz = pos[pv * 3 + 2];
        out[OFF_POSC + row * 3 + 0] = px;
        out[OFF_POSC + row * 3 + 1] = py;
        out[OFF_POSC + row * 3 + 2] = pz;

        g_posc[row] = make_float4(px, py, pz, sq_ref(px, py, pz));

        out[OFF_NT + row]    = (float)node_type[pv];
        out[OFF_BATCH + row] = (float)g;
    }
}

// ---------------------------------------------------------------------------
// Kernel 2: x_c = x[perm] @ W^T + b   (bit-exact ✓)
// ---------------------------------------------------------------------------
__global__ void gemm_kernel(const float* __restrict__ x,
                            const float* __restrict__ W,
                            const float* __restrict__ bias,
                            float* __restrict__ out) {
    __shared__ float Wsh[64 * 129];
    __shared__ float xs[16 * 64];
    __shared__ int   rows[16];

    const int t  = threadIdx.x;
    const int m0 = blockIdx.x * 16;

    if (t < 16) rows[t] = g_perm[m0 + t];

    float acc[16];
#pragma unroll
    for (int r = 0; r < 16; r++) acc[r] = 0.f;

    for (int kc = 0; kc < 2; kc++) {
        const int k0 = kc * 64;
        __syncthreads();
#pragma unroll
        for (int it = 0; it < 64; it++) {
            int idx = it * 128 + t;
            int c = idx >> 6;
            int k = idx & 63;
            Wsh[k * 129 + c] = W[c * 128 + k0 + k];
        }
#pragma unroll
        for (int it = 0; it < 8; it++) {
            int idx = it * 128 + t;
            int r = idx >> 6;
            int k = idx & 63;
            xs[r * 64 + k] = x[rows[r] * 128 + k0 + k];
        }
        __syncthreads();
#pragma unroll
        for (int k = 0; k < 64; k++) {
            float w = Wsh[k * 129 + t];
#pragma unroll
            for (int r = 0; r < 16; r++)
                acc[r] = fmaf(xs[r * 64 + k], w, acc[r]);
        }
    }

    float bb = bias[t];
#pragma unroll
    for (int r = 0; r < 16; r++)
        out[OFF_XC + (m0 + r) * 128 + t] = acc[r] + bb;
}

// ---------------------------------------------------------------------------
// Kernel 3: brute-force KNN (K=6); d2 per d2_ref; stable lower-index ties
// (strict '<' gate, strict '<' bubble).
// ---------------------------------------------------------------------------
__global__ void knn_kernel(float* __restrict__ out) {
    __shared__ float4 sh[2048];

    const int g    = blockIdx.x >> 5;
    const int q    = ((blockIdx.x & 31) << 8) + threadIdx.x;
    const int base = g * KK;

    const float4 qp = g_posc[base + q];

    float bd[6];
    int   bi[6];
#pragma unroll
    for (int m = 0; m < 6; m++) { bd[m] = CUDART_INF_F; bi[m] = 0; }

    for (int t0 = 0; t0 < KK; t0 += 2048) {
        __syncthreads();
        for (int j = threadIdx.x; j < 2048; j += 256)
            sh[j] = g_posc[base + t0 + j];
        __syncthreads();

#pragma unroll 4
        for (int j = 0; j < 2048; j++) {
            float d2 = d2_ref(qp, sh[j]);
            int   jl = t0 + j;
            if (jl != q && d2 < bd[5]) {
                bd[5] = d2; bi[5] = jl;
#pragma unroll
                for (int m = 5; m > 0; m--) {
                    if (bd[m] < bd[m - 1]) {
                        float td = bd[m]; bd[m] = bd[m - 1]; bd[m - 1] = td;
                        int   ti = bi[m]; bi[m] = bi[m - 1]; bi[m - 1] = ti;
                    }
                }
            }
        }
    }

    const int ig = base + q;
#pragma unroll
    for (int k = 0; k < KNN; k++) {
        int send = base + bi[k];
        int e    = ig * KNN + k;
        float4 ps = g_posc[send];
        float rx = __fsub_rn(ps.x, qp.x);
        float ry = __fsub_rn(ps.y, qp.y);
        float rz = __fsub_rn(ps.z, qp.z);
        // norm: same left-assoc contracted chain shape as sq, then sqrt
        float ss = __fmaf_rn(rz, rz, __fmaf_rn(rx, rx, __fmul_rn(ry, ry)));
        float nrm = sqrtf(ss);

        int ea0 = OFF_EA + e * 4;
        out[ea0 + 0] = rx;  out[ea0 + 1] = ry;  out[ea0 + 2] = rz;  out[ea0 + 3] = nrm;
        int ea1 = OFF_EA + (EE + e) * 4;
        out[ea1 + 0] = -rx; out[ea1 + 1] = -ry; out[ea1 + 2] = -rz; out[ea1 + 3] = nrm;

        out[OFF_EI + e]          = (float)send;
        out[OFF_EI + EE + e]     = (float)ig;
        out[OFF_EI + 2 * EE + e] = (float)ig;
        out[OFF_EI + 3 * EE + e] = (float)send;
    }
}

// ---------------------------------------------------------------------------
extern "C" void kernel_launch(void* const* d_in, const int* in_sizes, int n_in,
                              void* d_out, int out_size) {
    const float* x         = (const float*)d_in[0];
    const float* pos       = (const float*)d_in[1];
    const float* attn      = (const float*)d_in[2];
    const float* W         = (const float*)d_in[3];
    const float* b         = (const float*)d_in[4];
    const int*   node_type = (const int*)d_in[5];
    float* out = (float*)d_out;

    cudaFuncSetAttribute(topk_kernel,
                         cudaFuncAttributeMaxDynamicSharedMemorySize,
                         NN * (int)sizeof(unsigned long long));

    topk_kernel<<<BG, 1024, NN * sizeof(unsigned long long)>>>(attn, pos, node_type, out);
    gemm_kernel<<<TOTK / 16, 128>>>(x, W, b, out);
    knn_kernel<<<(TOTK + 255) / 256, 256>>>(out);
}